// round 15
// baseline (speedup 1.0000x reference)
#include <cuda_runtime.h>
#include <cuda_fp16.h>
#include <stdint.h>

#define CC 48
#define C3 144
#define HH 56
#define WW 56
#define HW 3136
#define NR 9216
#define DD 49
#define NT 36                     // key tiles per half
#define SQS 0.17158889f           // sqrt(log2(e)/49)

// ---------------- device scratch (allocation-free) ----------------
__device__ __half g_qk[NR * 64];             // s*yf f16; col 49 = s, 50..63 = 0
__device__ float g_opart[4 * NR * 64];       // raw partial O (den at col 49)
__device__ float g_pwpart[2 * 64 * CC * 52]; // pw partials [ig][win][o][52]

// ---------------- PTX helpers ----------------
__device__ __forceinline__ uint32_t smem_u32(const void* p) {
    uint32_t a;
    asm("{ .reg .u64 t; cvta.to.shared.u64 t, %1; cvt.u32.u64 %0, t; }"
        : "=r"(a) : "l"(p));
    return a;
}
#define SW128(o) ((o) ^ (((o) >> 3) & 0x70))

__device__ __forceinline__ float fast_rcp(float x) {
    float y;
    asm("rcp.approx.ftz.f32 %0, %1;" : "=f"(y) : "f"(x));
    return y;
}

__device__ __forceinline__ uint32_t ex2_h2(uint32_t h) {
    uint32_t r;
    asm("ex2.approx.f16x2 %0, %1;" : "=r"(r) : "r"(h));
    return r;
}

#define CP_ASYNC16(dst, src) \
    asm volatile("cp.async.cg.shared.global [%0], [%1], 16;" :: "r"(dst), "l"(src))
#define CP_COMMIT() asm volatile("cp.async.commit_group;" ::: "memory")
#define CP_WAIT0()  asm volatile("cp.async.wait_group 0;" ::: "memory")
#define CP_WAIT1()  asm volatile("cp.async.wait_group 1;" ::: "memory")

#define LDSM_X4(r0, r1, r2, r3, a) \
    asm volatile("ldmatrix.sync.aligned.m8n8.x4.shared.b16 {%0,%1,%2,%3}, [%4];" \
                 : "=r"(r0), "=r"(r1), "=r"(r2), "=r"(r3) : "r"(a))
#define LDSM_X4T(r0, r1, r2, r3, a) \
    asm volatile("ldmatrix.sync.aligned.m8n8.x4.trans.shared.b16 {%0,%1,%2,%3}, [%4];" \
                 : "=r"(r0), "=r"(r1), "=r"(r2), "=r"(r3) : "r"(a))

// f32-accum HMMA (PV phase)
#define MMA(d, a0, a1, a2, a3, b0, b1) \
    asm volatile("mma.sync.aligned.m16n8k16.row.col.f32.f16.f16.f32 " \
                 "{%0,%1,%2,%3}, {%4,%5,%6,%7}, {%8,%9}, {%0,%1,%2,%3};" \
                 : "+f"((d)[0]), "+f"((d)[1]), "+f"((d)[2]), "+f"((d)[3]) \
                 : "r"(a0), "r"(a1), "r"(a2), "r"(a3), "r"(b0), "r"(b1))

// f16-accum HMMA (S phase): D fragment == PV A-fragment layout
#define MMAH(d, a0, a1, a2, a3, b0, b1) \
    asm volatile("mma.sync.aligned.m16n8k16.row.col.f16.f16.f16.f16 " \
                 "{%0,%1}, {%2,%3,%4,%5}, {%6,%7}, {%0,%1};" \
                 : "+r"((d)[0]), "+r"((d)[1]) \
                 : "r"(a0), "r"(a1), "r"(a2), "r"(a3), "r"(b0), "r"(b1))

// ---------------------------------------------------------------------------
// Kernel A: depthwise convs in packed f16x2, balanced tasks.
// ---------------------------------------------------------------------------
template<int K, int OFF, int WB, int NP>
__device__ __forceinline__ void conv_task(const __half xsh[13][132],
                                          const __half2* sw2,
                                          int ho, int w0, __half2 acc[NP]) {
    #pragma unroll
    for (int dh = 0; dh < K; dh++) {
        const __half* row = xsh[ho + dh + OFF];
        __half2 xv[2 * NP + K - 2];
        #pragma unroll
        for (int t = 0; t < 2 * NP + K - 2; t++)
            xv[t] = *(const __half2*)&row[2 * (w0 + OFF + t)];
        #pragma unroll
        for (int dw = 0; dw < K; dw++) {
            __half2 wt = sw2[WB + dh * K + dw];
            #pragma unroll
            for (int j = 0; j < NP; j++)
                acc[j] = __hfma2(xv[2 * j + dw], wt, acc[j]);
        }
    }
}

__global__ void __launch_bounds__(256) conv_kernel(const float* __restrict__ x,
                                                   const float* __restrict__ w3,
                                                   const float* __restrict__ w5,
                                                   const float* __restrict__ w7) {
    __shared__ __half  xsh[13][132];
    __shared__ __half2 sw2[83];

    const int tid = threadIdx.x;
    const int c   = blockIdx.x >> 3;
    const int h0  = (blockIdx.x & 7) * 7;

    for (int j = blockIdx.x * 256 + tid; j < NR * 15; j += 384 * 256) {
        int r = j / 15, cc = j - r * 15;
        g_qk[r * 64 + 49 + cc] = __float2half(cc == 0 ? SQS : 0.f);
    }

    const float* xc = x + c * HW;
    for (int idx = tid; idx < 13 * 64; idx += 256) {
        int r = idx >> 6, wc = idx & 63;
        int hh = h0 - 3 + r, w = wc - 3;
        float v = 0.f;
        if (hh >= 0 && hh < HH && w >= 0 && w < WW) v = xc[hh * WW + w];
        __half hv = __float2half(v);
        xsh[r][2 * wc] = hv;
        if (wc > 0) xsh[r][2 * wc - 1] = hv;
    }
    if (tid < 83) {
        float v;
        if (tid < 9)       v = w3[c * 9 + tid];
        else if (tid < 34) v = w5[c * 25 + tid - 9];
        else               v = w7[c * 49 + tid - 34];
        sw2[tid] = __float2half2_rn(v * SQS);
    }
    __syncthreads();

    const __half2 z2 = __float2half2_rn(0.f);

    if (tid < 49) {
        int ho = tid / 7, w0 = (tid - ho * 7) * 8;
        __half2 acc[4] = {z2, z2, z2, z2};
        conv_task<3, 2, 0, 4>(xsh, sw2, ho, w0, acc);
        #pragma unroll
        for (int j = 0; j < 4; j++) {
            int lin = (h0 + ho) * WW + w0 + 2 * j;
            int g = lin / DD, p = lin - g * DD;
            g_qk[(g * C3 + c) * 64 + p] = __low2half(acc[j]);
            lin++;
            g = lin / DD; p = lin - g * DD;
            g_qk[(g * C3 + c) * 64 + p] = __high2half(acc[j]);
        }
    } else if (tid < 245) {
        int b   = (tid < 147) ? 1 : 2;
        int r   = tid - (b == 1 ? 49 : 147);
        int sub = r / 49;
        int r49 = r - sub * 49;
        int ho  = r49 / 7;
        int w0  = (r49 - ho * 7) * 8 + sub * 4;

        __half2 acc[2] = {z2, z2};
        if (b == 1) conv_task<5, 1, 9, 2>(xsh, sw2, ho, w0, acc);
        else        conv_task<7, 0, 34, 2>(xsh, sw2, ho, w0, acc);

        const int c3 = b * CC + c;
        #pragma unroll
        for (int j = 0; j < 2; j++) {
            int lin = (h0 + ho) * WW + w0 + 2 * j;
            int g = lin / DD, p = lin - g * DD;
            g_qk[(g * C3 + c3) * 64 + p] = __low2half(acc[j]);
            lin++;
            g = lin / DD; p = lin - g * DD;
            g_qk[(g * C3 + c3) * 64 + p] = __high2half(acc[j]);
        }
    }
}

// ---------------------------------------------------------------------------
// Kernel B: flash attention. S in f16-accum HMMA (D frag == PV A frag),
// exp = single ex2.approx.f16x2 on raw D registers. PV in f32-accum.
// ---------------------------------------------------------------------------
__global__ void __launch_bounds__(256, 1) attn_kernel() {
    extern __shared__ char smraw[];
    const uint32_t SB  = smem_u32(smraw);
    const uint32_t QB  = SB;
    const uint32_t KB0 = SB + 16384;

    const int tid  = threadIdx.x;
    const int lane = tid & 31;
    const int wid  = tid >> 5;
    const int wm = wid >> 1, wn = wid & 1;
    const int g = lane >> 2, tig = lane & 3;
    const int bq = blockIdx.x >> 1, half = blockIdx.x & 1;
    const int q0 = bq * 128;

    const int l7 = lane & 7;
    const uint32_t xm   = (uint32_t)(l7 << 4);
    const uint32_t aoff = (uint32_t)((wm * 32 + l7 + ((lane & 8) ? 8 : 0)) * 128);
    const uint32_t ahi  = (lane & 16) ? 16u : 0u;
    const uint32_t bsb  = (uint32_t)((wn * 64 + l7 + ((lane & 16) ? 8 : 0)) * 128);
    const uint32_t bshi = (lane & 8) ? 16u : 0u;
    const uint32_t bvb  = (uint32_t)((wn * 64 + l7 + ((lane & 8) ? 8 : 0)) * 128);
    const uint32_t bvhi = (lane & 16) ? 16u : 0u;

    {
        const char* src = (const char*)g_qk + (size_t)q0 * 128;
        #pragma unroll
        for (int it = 0; it < 4; it++) {
            int idx = it * 256 + tid;
            int r = idx >> 3, c = idx & 7;
            CP_ASYNC16(QB + SW128((uint32_t)(r * 128 + c * 16)), src + r * 128 + c * 16);
        }
        CP_COMMIT();
    }
    {
        const char* src = (const char*)g_qk + (size_t)(half * 4608) * 128;
        #pragma unroll
        for (int it = 0; it < 4; it++) {
            int idx = it * 256 + tid;
            int r = idx >> 3, c = idx & 7;
            CP_ASYNC16(KB0 + SW128((uint32_t)(r * 128 + c * 16)), src + r * 128 + c * 16);
        }
        CP_COMMIT();
    }

    CP_WAIT1();
    __syncthreads();
    uint32_t Af[2][4][4];
    #pragma unroll
    for (int ks = 0; ks < 4; ks++) {
        uint32_t ac = (uint32_t)(ks * 32 + ahi) ^ xm;
        LDSM_X4(Af[0][ks][0], Af[0][ks][1], Af[0][ks][2], Af[0][ks][3],
                QB + aoff + ac);
        LDSM_X4(Af[1][ks][0], Af[1][ks][1], Af[1][ks][2], Af[1][ks][3],
                QB + aoff + 2048 + ac);
    }

    float Ov[2][7][4] = {};

    for (int t = 0; t < NT; t++) {
        CP_WAIT0();
        __syncthreads();
        if (t + 1 < NT) {
            const uint32_t kb = KB0 + (uint32_t)(((t + 1) & 1) * 16384);
            const char* src = (const char*)g_qk + (size_t)(half * 4608 + (t + 1) * 128) * 128;
            #pragma unroll
            for (int it = 0; it < 4; it++) {
                int idx = it * 256 + tid;
                int r = idx >> 3, c = idx & 7;
                CP_ASYNC16(kb + SW128((uint32_t)(r * 128 + c * 16)), src + r * 128 + c * 16);
            }
            CP_COMMIT();
        }

        const uint32_t KB = KB0 + (uint32_t)((t & 1) * 16384);

        // ---- S = Q K^T in f16 accumulation ----
        uint32_t Cs[2][8][2] = {};
        #pragma unroll
        for (int ks = 0; ks < 4; ks++) {
            uint32_t bc = (uint32_t)(ks * 32 + bshi) ^ xm;
            #pragma unroll
            for (int np = 0; np < 4; np++) {
                uint32_t B[4];
                LDSM_X4(B[0], B[1], B[2], B[3], KB + bsb + (uint32_t)(np * 2048) + bc);
                MMAH(Cs[0][2 * np],     Af[0][ks][0], Af[0][ks][1], Af[0][ks][2], Af[0][ks][3], B[0], B[1]);
                MMAH(Cs[0][2 * np + 1], Af[0][ks][0], Af[0][ks][1], Af[0][ks][2], Af[0][ks][3], B[2], B[3]);
                MMAH(Cs[1][2 * np],     Af[1][ks][0], Af[1][ks][1], Af[1][ks][2], Af[1][ks][3], B[0], B[1]);
                MMAH(Cs[1][2 * np + 1], Af[1][ks][0], Af[1][ks][1], Af[1][ks][2], Af[1][ks][3], B[2], B[3]);
            }
        }

        // ---- exp directly on f16x2 D regs -> PV A fragments ----
        #pragma unroll
        for (int ks = 0; ks < 4; ks++) {
            uint32_t aP[2][4];
            #pragma unroll
            for (int m = 0; m < 2; m++) {
                aP[m][0] = ex2_h2(Cs[m][2 * ks][0]);
                aP[m][1] = ex2_h2(Cs[m][2 * ks][1]);
                aP[m][2] = ex2_h2(Cs[m][2 * ks + 1][0]);
                aP[m][3] = ex2_h2(Cs[m][2 * ks + 1][1]);
            }
            #pragma unroll
            for (int dp = 0; dp < 4; dp++) {
                uint32_t B[4];
                LDSM_X4T(B[0], B[1], B[2], B[3],
                         KB + bvb + (uint32_t)(ks * 2048) +
                         (((uint32_t)(dp * 32 + bvhi)) ^ xm));
                MMA(Ov[0][2 * dp], aP[0][0], aP[0][1], aP[0][2], aP[0][3], B[0], B[1]);
                MMA(Ov[1][2 * dp], aP[1][0], aP[1][1], aP[1][2], aP[1][3], B[0], B[1]);
                if (dp < 3) {
                    MMA(Ov[0][2 * dp + 1], aP[0][0], aP[0][1], aP[0][2], aP[0][3], B[2], B[3]);
                    MMA(Ov[1][2 * dp + 1], aP[1][0], aP[1][1], aP[1][2], aP[1][3], B[2], B[3]);
                }
            }
        }
    }

    const int part = half * 2 + wn;
    #pragma unroll
    for (int m = 0; m < 2; m++) {
        int r0 = q0 + wm * 32 + m * 16 + g;
        float* base = g_opart + ((size_t)part * NR + r0) * 64;
        #pragma unroll
        for (int nt = 0; nt < 7; nt++) {
            int col = nt * 8 + 2 * tig;
            *(float2*)(base + col)          = make_float2(Ov[m][nt][0], Ov[m][nt][1]);
            *(float2*)(base + 8 * 64 + col) = make_float2(Ov[m][nt][2], Ov[m][nt][3]);
        }
    }
}

// ---------------------------------------------------------------------------
// Kernel C: pw partial GEMM. Grid = 64 windows x 2 i-halves.
// ---------------------------------------------------------------------------
__global__ void __launch_bounds__(256) pw_part(const float* __restrict__ pww) {
    __shared__ float sh_y[72][52];
    __shared__ float sh_w[72][48];
    __shared__ float sh_rd[72];

    const int tid = threadIdx.x;
    const int win = blockIdx.x >> 1;
    const int ig  = blockIdx.x & 1;
    const int i0  = ig * 72;

    if (tid < 72) {
        int r = win * C3 + i0 + tid;
        float den = g_opart[r * 64 + 49] + g_opart[NR * 64 + r * 64 + 49] +
                    g_opart[2 * NR * 64 + r * 64 + 49] + g_opart[3 * NR * 64 + r * 64 + 49];
        sh_rd[tid] = fast_rcp(den);
    }
    __syncthreads();

    for (int idx = tid; idx < 72 * 13; idx += 256) {
        int i = idx / 13, q = idx - i * 13;
        int r = win * C3 + i0 + i;
        int base = r * 64 + 4 * q;
        float4 a = *(const float4*)(g_opart + base);
        float4 b = *(const float4*)(g_opart + NR * 64 + base);
        float4 c = *(const float4*)(g_opart + 2 * NR * 64 + base);
        float4 d = *(const float4*)(g_opart + 3 * NR * 64 + base);
        float rd = sh_rd[i];
        float4 o;
        o.x = (a.x + b.x + c.x + d.x) * rd;
        o.y = (a.y + b.y + c.y + d.y) * rd;
        o.z = (a.z + b.z + c.z + d.z) * rd;
        o.w = (a.w + b.w + c.w + d.w) * rd;
        *(float4*)&sh_y[i][4 * q] = o;
    }
    for (int idx = tid; idx < 72 * 48; idx += 256) {
        int i = idx / 48, o = idx - i * 48;
        sh_w[i][o] = pww[o * C3 + i0 + i];
    }
    __syncthreads();

    if (tid < 156) {
        const int ot = tid / 13, pg = tid - ot * 13;
        const int o0 = 4 * ot, p0 = 4 * pg;
        float acc[4][4] = {};
        #pragma unroll 8
        for (int i = 0; i < 72; i++) {
            float4 y = *(const float4*)&sh_y[i][p0];
            float4 w = *(const float4*)&sh_w[i][o0];
            acc[0][0] += w.x * y.x; acc[0][1] += w.x * y.y; acc[0][2] += w.x * y.z; acc[0][3] += w.x * y.w;
            acc[1][0] += w.y * y.x; acc[1][1] += w.y * y.y; acc[1][2] += w.y * y.z; acc[1][3] += w.y * y.w;
            acc[2][0] += w.z * y.x; acc[2][1] += w.z * y.y; acc[2][2] += w.z * y.z; acc[2][3] += w.z * y.w;
            acc[3][0] += w.w * y.x; acc[3][1] += w.w * y.y; acc[3][2] += w.w * y.z; acc[3][3] += w.w * y.w;
        }
        float* base = g_pwpart + ((size_t)(ig * 64 + win) * CC + o0) * 52 + p0;
        #pragma unroll
        for (int j = 0; j < 4; j++)
            *(float4*)(base + j * 52) =
                make_float4(acc[j][0], acc[j][1], acc[j][2], acc[j][3]);
    }
}

// ---------------------------------------------------------------------------
// Kernel D: final sum + bias + residual, float4 along w.
// ---------------------------------------------------------------------------
__global__ void __launch_bounds__(256) pw_final(const float* __restrict__ x,
                                                const float* __restrict__ pb,
                                                float* __restrict__ out) {
    int t = blockIdx.x * 256 + threadIdx.x;
    if (t >= CC * HW / 4) return;
    int o   = t / (HW / 4);
    int rem = t - o * (HW / 4);
    int h   = rem / 14;
    int w0  = (rem - h * 14) * 4;
    int gi  = o * HW + h * WW + w0;
    float4 xv = *(const float4*)(x + gi);
    float bias = pb[o];
    const int whb = (h / 7) * 8;
    const int pb7 = (h % 7) * 7;
    float vo[4];
    const float* pxv = (const float*)&xv;
    #pragma unroll
    for (int j = 0; j < 4; j++) {
        int w   = w0 + j;
        int win = whb + w / 7;
        int p   = pb7 + w % 7;
        float v = g_pwpart[((size_t)win * CC + o) * 52 + p] +
                  g_pwpart[((size_t)(64 + win) * CC + o) * 52 + p];
        vo[j] = pxv[j] + bias + v;
    }
    *(float4*)(out + gi) = make_float4(vo[0], vo[1], vo[2], vo[3]);
}

// ---------------------------------------------------------------------------
extern "C" void kernel_launch(void* const* d_in, const int* in_sizes, int n_in,
                              void* d_out, int out_size) {
    const float* x  = (const float*)d_in[0];
    const float* w3 = (const float*)d_in[1];
    const float* w5 = (const float*)d_in[2];
    const float* w7 = (const float*)d_in[3];
    const float* pw = (const float*)d_in[4];
    const float* pb = (const float*)d_in[5];
    float* out = (float*)d_out;

    cudaFuncSetAttribute(attn_kernel,
                         cudaFuncAttributeMaxDynamicSharedMemorySize, 49152);

    conv_kernel<<<384, 256>>>(x, w3, w5, w7);
    attn_kernel<<<144, 256, 49152>>>();
    pw_part<<<128, 256>>>(pw);
    pw_final<<<(CC * HW / 4 + 255) / 256, 256>>>(x, pb, out);
}

// round 16
// speedup vs baseline: 1.0379x; 1.0379x over previous
#include <cuda_runtime.h>
#include <cuda_fp16.h>
#include <stdint.h>

#define CC 48
#define C3 144
#define HH 56
#define WW 56
#define HW 3136
#define NR 9216
#define DD 49
#define NT 24                     // key tiles per half (BN=192)
#define SQS 0.17158889f           // sqrt(log2(e)/49)

// ---------------- device scratch (allocation-free) ----------------
__device__ __half g_qk[NR * 64];             // s*yf f16; col 49 = s, 50..63 = 0
__device__ float g_opart[4 * NR * 64];       // raw partial O (den at col 49)
__device__ float g_pwpart[2 * 64 * CC * 52]; // pw partials [ig][win][o][52]

// ---------------- PTX helpers ----------------
__device__ __forceinline__ uint32_t smem_u32(const void* p) {
    uint32_t a;
    asm("{ .reg .u64 t; cvta.to.shared.u64 t, %1; cvt.u32.u64 %0, t; }"
        : "=r"(a) : "l"(p));
    return a;
}
#define SW128(o) ((o) ^ (((o) >> 3) & 0x70))

__device__ __forceinline__ float fast_rcp(float x) {
    float y;
    asm("rcp.approx.ftz.f32 %0, %1;" : "=f"(y) : "f"(x));
    return y;
}

__device__ __forceinline__ uint32_t ex2_h2(uint32_t h) {
    uint32_t r;
    asm("ex2.approx.f16x2 %0, %1;" : "=r"(r) : "r"(h));
    return r;
}

#define CP_ASYNC16(dst, src) \
    asm volatile("cp.async.cg.shared.global [%0], [%1], 16;" :: "r"(dst), "l"(src))
#define CP_COMMIT() asm volatile("cp.async.commit_group;" ::: "memory")
#define CP_WAIT0()  asm volatile("cp.async.wait_group 0;" ::: "memory")
#define CP_WAIT1()  asm volatile("cp.async.wait_group 1;" ::: "memory")

#define LDSM_X4(r0, r1, r2, r3, a) \
    asm volatile("ldmatrix.sync.aligned.m8n8.x4.shared.b16 {%0,%1,%2,%3}, [%4];" \
                 : "=r"(r0), "=r"(r1), "=r"(r2), "=r"(r3) : "r"(a))
#define LDSM_X4T(r0, r1, r2, r3, a) \
    asm volatile("ldmatrix.sync.aligned.m8n8.x4.trans.shared.b16 {%0,%1,%2,%3}, [%4];" \
                 : "=r"(r0), "=r"(r1), "=r"(r2), "=r"(r3) : "r"(a))

// f32-accum HMMA (PV phase)
#define MMA(d, a0, a1, a2, a3, b0, b1) \
    asm volatile("mma.sync.aligned.m16n8k16.row.col.f32.f16.f16.f32 " \
                 "{%0,%1,%2,%3}, {%4,%5,%6,%7}, {%8,%9}, {%0,%1,%2,%3};" \
                 : "+f"((d)[0]), "+f"((d)[1]), "+f"((d)[2]), "+f"((d)[3]) \
                 : "r"(a0), "r"(a1), "r"(a2), "r"(a3), "r"(b0), "r"(b1))

// f16-accum HMMA (S phase): D fragment == PV A-fragment layout
#define MMAH(d, a0, a1, a2, a3, b0, b1) \
    asm volatile("mma.sync.aligned.m16n8k16.row.col.f16.f16.f16.f16 " \
                 "{%0,%1}, {%2,%3,%4,%5}, {%6,%7}, {%0,%1};" \
                 : "+r"((d)[0]), "+r"((d)[1]) \
                 : "r"(a0), "r"(a1), "r"(a2), "r"(a3), "r"(b0), "r"(b1))

// ---------------------------------------------------------------------------
// Kernel A: depthwise convs in packed f16x2, balanced tasks.
// ---------------------------------------------------------------------------
template<int K, int OFF, int WB, int NP>
__device__ __forceinline__ void conv_task(const __half xsh[13][132],
                                          const __half2* sw2,
                                          int ho, int w0, __half2 acc[NP]) {
    #pragma unroll
    for (int dh = 0; dh < K; dh++) {
        const __half* row = xsh[ho + dh + OFF];
        __half2 xv[2 * NP + K - 2];
        #pragma unroll
        for (int t = 0; t < 2 * NP + K - 2; t++)
            xv[t] = *(const __half2*)&row[2 * (w0 + OFF + t)];
        #pragma unroll
        for (int dw = 0; dw < K; dw++) {
            __half2 wt = sw2[WB + dh * K + dw];
            #pragma unroll
            for (int j = 0; j < NP; j++)
                acc[j] = __hfma2(xv[2 * j + dw], wt, acc[j]);
        }
    }
}

__global__ void __launch_bounds__(256) conv_kernel(const float* __restrict__ x,
                                                   const float* __restrict__ w3,
                                                   const float* __restrict__ w5,
                                                   const float* __restrict__ w7) {
    __shared__ __half  xsh[13][132];
    __shared__ __half2 sw2[83];

    const int tid = threadIdx.x;
    const int c   = blockIdx.x >> 3;
    const int h0  = (blockIdx.x & 7) * 7;

    for (int j = blockIdx.x * 256 + tid; j < NR * 15; j += 384 * 256) {
        int r = j / 15, cc = j - r * 15;
        g_qk[r * 64 + 49 + cc] = __float2half(cc == 0 ? SQS : 0.f);
    }

    const float* xc = x + c * HW;
    for (int idx = tid; idx < 13 * 64; idx += 256) {
        int r = idx >> 6, wc = idx & 63;
        int hh = h0 - 3 + r, w = wc - 3;
        float v = 0.f;
        if (hh >= 0 && hh < HH && w >= 0 && w < WW) v = xc[hh * WW + w];
        __half hv = __float2half(v);
        xsh[r][2 * wc] = hv;
        if (wc > 0) xsh[r][2 * wc - 1] = hv;
    }
    if (tid < 83) {
        float v;
        if (tid < 9)       v = w3[c * 9 + tid];
        else if (tid < 34) v = w5[c * 25 + tid - 9];
        else               v = w7[c * 49 + tid - 34];
        sw2[tid] = __float2half2_rn(v * SQS);
    }
    __syncthreads();

    const __half2 z2 = __float2half2_rn(0.f);

    if (tid < 49) {
        int ho = tid / 7, w0 = (tid - ho * 7) * 8;
        __half2 acc[4] = {z2, z2, z2, z2};
        conv_task<3, 2, 0, 4>(xsh, sw2, ho, w0, acc);
        #pragma unroll
        for (int j = 0; j < 4; j++) {
            int lin = (h0 + ho) * WW + w0 + 2 * j;
            int g = lin / DD, p = lin - g * DD;
            g_qk[(g * C3 + c) * 64 + p] = __low2half(acc[j]);
            lin++;
            g = lin / DD; p = lin - g * DD;
            g_qk[(g * C3 + c) * 64 + p] = __high2half(acc[j]);
        }
    } else if (tid < 245) {
        int b   = (tid < 147) ? 1 : 2;
        int r   = tid - (b == 1 ? 49 : 147);
        int sub = r / 49;
        int r49 = r - sub * 49;
        int ho  = r49 / 7;
        int w0  = (r49 - ho * 7) * 8 + sub * 4;

        __half2 acc[2] = {z2, z2};
        if (b == 1) conv_task<5, 1, 9, 2>(xsh, sw2, ho, w0, acc);
        else        conv_task<7, 0, 34, 2>(xsh, sw2, ho, w0, acc);

        const int c3 = b * CC + c;
        #pragma unroll
        for (int j = 0; j < 2; j++) {
            int lin = (h0 + ho) * WW + w0 + 2 * j;
            int g = lin / DD, p = lin - g * DD;
            g_qk[(g * C3 + c3) * 64 + p] = __low2half(acc[j]);
            lin++;
            g = lin / DD; p = lin - g * DD;
            g_qk[(g * C3 + c3) * 64 + p] = __high2half(acc[j]);
        }
    }
}

// ---------------------------------------------------------------------------
// Kernel B: flash attention, BN=192 (24 tiles/half). S in f16-accum HMMA,
// exp = ex2.approx.f16x2 on raw D regs, PV f32-accum.
// SMEM: Q 16K | K double buffer 2x24K = 64K.
// ---------------------------------------------------------------------------
#define KBUF 24576
__global__ void __launch_bounds__(256, 1) attn_kernel() {
    extern __shared__ char smraw[];
    const uint32_t SB  = smem_u32(smraw);
    const uint32_t QB  = SB;
    const uint32_t KB0 = SB + 16384;

    const int tid  = threadIdx.x;
    const int lane = tid & 31;
    const int wid  = tid >> 5;
    const int wm = wid >> 1, wn = wid & 1;
    const int g = lane >> 2, tig = lane & 3;
    const int bq = blockIdx.x >> 1, half = blockIdx.x & 1;
    const int q0 = bq * 128;

    const int l7 = lane & 7;
    const uint32_t xm   = (uint32_t)(l7 << 4);
    const uint32_t aoff = (uint32_t)((wm * 32 + l7 + ((lane & 8) ? 8 : 0)) * 128);
    const uint32_t ahi  = (lane & 16) ? 16u : 0u;
    const uint32_t bsb  = (uint32_t)((wn * 96 + l7 + ((lane & 16) ? 8 : 0)) * 128);
    const uint32_t bshi = (lane & 8) ? 16u : 0u;
    const uint32_t bvb  = (uint32_t)((wn * 96 + l7 + ((lane & 8) ? 8 : 0)) * 128);
    const uint32_t bvhi = (lane & 16) ? 16u : 0u;

    {
        const char* src = (const char*)g_qk + (size_t)q0 * 128;
        #pragma unroll
        for (int it = 0; it < 4; it++) {
            int idx = it * 256 + tid;
            int r = idx >> 3, c = idx & 7;
            CP_ASYNC16(QB + SW128((uint32_t)(r * 128 + c * 16)), src + r * 128 + c * 16);
        }
        CP_COMMIT();
    }
    {
        const char* src = (const char*)g_qk + (size_t)(half * 4608) * 128;
        #pragma unroll
        for (int it = 0; it < 6; it++) {
            int idx = it * 256 + tid;
            int r = idx >> 3, c = idx & 7;
            CP_ASYNC16(KB0 + SW128((uint32_t)(r * 128 + c * 16)), src + r * 128 + c * 16);
        }
        CP_COMMIT();
    }

    CP_WAIT1();
    __syncthreads();
    uint32_t Af[2][4][4];
    #pragma unroll
    for (int ks = 0; ks < 4; ks++) {
        uint32_t ac = (uint32_t)(ks * 32 + ahi) ^ xm;
        LDSM_X4(Af[0][ks][0], Af[0][ks][1], Af[0][ks][2], Af[0][ks][3],
                QB + aoff + ac);
        LDSM_X4(Af[1][ks][0], Af[1][ks][1], Af[1][ks][2], Af[1][ks][3],
                QB + aoff + 2048 + ac);
    }

    float Ov[2][7][4] = {};

    for (int t = 0; t < NT; t++) {
        CP_WAIT0();
        __syncthreads();
        if (t + 1 < NT) {
            const uint32_t kb = KB0 + (uint32_t)(((t + 1) & 1) * KBUF);
            const char* src = (const char*)g_qk + (size_t)(half * 4608 + (t + 1) * 192) * 128;
            #pragma unroll
            for (int it = 0; it < 6; it++) {
                int idx = it * 256 + tid;
                int r = idx >> 3, c = idx & 7;
                CP_ASYNC16(kb + SW128((uint32_t)(r * 128 + c * 16)), src + r * 128 + c * 16);
            }
            CP_COMMIT();
        }

        const uint32_t KB = KB0 + (uint32_t)((t & 1) * KBUF);

        // ---- S = Q K^T in f16 accumulation: per warp 32 rows x 96 keys ----
        uint32_t Cs[2][12][2] = {};
        #pragma unroll
        for (int ks = 0; ks < 4; ks++) {
            uint32_t bc = (uint32_t)(ks * 32 + bshi) ^ xm;
            #pragma unroll
            for (int np = 0; np < 6; np++) {
                uint32_t B[4];
                LDSM_X4(B[0], B[1], B[2], B[3], KB + bsb + (uint32_t)(np * 2048) + bc);
                MMAH(Cs[0][2 * np],     Af[0][ks][0], Af[0][ks][1], Af[0][ks][2], Af[0][ks][3], B[0], B[1]);
                MMAH(Cs[0][2 * np + 1], Af[0][ks][0], Af[0][ks][1], Af[0][ks][2], Af[0][ks][3], B[2], B[3]);
                MMAH(Cs[1][2 * np],     Af[1][ks][0], Af[1][ks][1], Af[1][ks][2], Af[1][ks][3], B[0], B[1]);
                MMAH(Cs[1][2 * np + 1], Af[1][ks][0], Af[1][ks][1], Af[1][ks][2], Af[1][ks][3], B[2], B[3]);
            }
        }

        // ---- exp on f16x2 D regs -> PV A fragments; 6 groups of 16 keys ----
        #pragma unroll
        for (int ks = 0; ks < 6; ks++) {
            uint32_t aP[2][4];
            #pragma unroll
            for (int m = 0; m < 2; m++) {
                aP[m][0] = ex2_h2(Cs[m][2 * ks][0]);
                aP[m][1] = ex2_h2(Cs[m][2 * ks][1]);
                aP[m][2] = ex2_h2(Cs[m][2 * ks + 1][0]);
                aP[m][3] = ex2_h2(Cs[m][2 * ks + 1][1]);
            }
            #pragma unroll
            for (int dp = 0; dp < 4; dp++) {
                uint32_t B[4];
                LDSM_X4T(B[0], B[1], B[2], B[3],
                         KB + bvb + (uint32_t)(ks * 2048) +
                         (((uint32_t)(dp * 32 + bvhi)) ^ xm));
                MMA(Ov[0][2 * dp], aP[0][0], aP[0][1], aP[0][2], aP[0][3], B[0], B[1]);
                MMA(Ov[1][2 * dp], aP[1][0], aP[1][1], aP[1][2], aP[1][3], B[0], B[1]);
                if (dp < 3) {
                    MMA(Ov[0][2 * dp + 1], aP[0][0], aP[0][1], aP[0][2], aP[0][3], B[2], B[3]);
                    MMA(Ov[1][2 * dp + 1], aP[1][0], aP[1][1], aP[1][2], aP[1][3], B[2], B[3]);
                }
            }
        }
    }

    const int part = half * 2 + wn;
    #pragma unroll
    for (int m = 0; m < 2; m++) {
        int r0 = q0 + wm * 32 + m * 16 + g;
        float* base = g_opart + ((size_t)part * NR + r0) * 64;
        #pragma unroll
        for (int nt = 0; nt < 7; nt++) {
            int col = nt * 8 + 2 * tig;
            *(float2*)(base + col)          = make_float2(Ov[m][nt][0], Ov[m][nt][1]);
            *(float2*)(base + 8 * 64 + col) = make_float2(Ov[m][nt][2], Ov[m][nt][3]);
        }
    }
}

// ---------------------------------------------------------------------------
// Kernel C: pw partial GEMM. Grid = 64 windows x 2 i-halves.
// ---------------------------------------------------------------------------
__global__ void __launch_bounds__(256) pw_part(const float* __restrict__ pww) {
    __shared__ float sh_y[72][52];
    __shared__ float sh_w[72][48];
    __shared__ float sh_rd[72];

    const int tid = threadIdx.x;
    const int win = blockIdx.x >> 1;
    const int ig  = blockIdx.x & 1;
    const int i0  = ig * 72;

    if (tid < 72) {
        int r = win * C3 + i0 + tid;
        float den = g_opart[r * 64 + 49] + g_opart[NR * 64 + r * 64 + 49] +
                    g_opart[2 * NR * 64 + r * 64 + 49] + g_opart[3 * NR * 64 + r * 64 + 49];
        sh_rd[tid] = fast_rcp(den);
    }
    __syncthreads();

    for (int idx = tid; idx < 72 * 13; idx += 256) {
        int i = idx / 13, q = idx - i * 13;
        int r = win * C3 + i0 + i;
        int base = r * 64 + 4 * q;
        float4 a = *(const float4*)(g_opart + base);
        float4 b = *(const float4*)(g_opart + NR * 64 + base);
        float4 c = *(const float4*)(g_opart + 2 * NR * 64 + base);
        float4 d = *(const float4*)(g_opart + 3 * NR * 64 + base);
        float rd = sh_rd[i];
        float4 o;
        o.x = (a.x + b.x + c.x + d.x) * rd;
        o.y = (a.y + b.y + c.y + d.y) * rd;
        o.z = (a.z + b.z + c.z + d.z) * rd;
        o.w = (a.w + b.w + c.w + d.w) * rd;
        *(float4*)&sh_y[i][4 * q] = o;
    }
    for (int idx = tid; idx < 72 * 48; idx += 256) {
        int i = idx / 48, o = idx - i * 48;
        sh_w[i][o] = pww[o * C3 + i0 + i];
    }
    __syncthreads();

    if (tid < 156) {
        const int ot = tid / 13, pg = tid - ot * 13;
        const int o0 = 4 * ot, p0 = 4 * pg;
        float acc[4][4] = {};
        #pragma unroll 8
        for (int i = 0; i < 72; i++) {
            float4 y = *(const float4*)&sh_y[i][p0];
            float4 w = *(const float4*)&sh_w[i][o0];
            acc[0][0] += w.x * y.x; acc[0][1] += w.x * y.y; acc[0][2] += w.x * y.z; acc[0][3] += w.x * y.w;
            acc[1][0] += w.y * y.x; acc[1][1] += w.y * y.y; acc[1][2] += w.y * y.z; acc[1][3] += w.y * y.w;
            acc[2][0] += w.z * y.x; acc[2][1] += w.z * y.y; acc[2][2] += w.z * y.z; acc[2][3] += w.z * y.w;
            acc[3][0] += w.w * y.x; acc[3][1] += w.w * y.y; acc[3][2] += w.w * y.z; acc[3][3] += w.w * y.w;
        }
        float* base = g_pwpart + ((size_t)(ig * 64 + win) * CC + o0) * 52 + p0;
        #pragma unroll
        for (int j = 0; j < 4; j++)
            *(float4*)(base + j * 52) =
                make_float4(acc[j][0], acc[j][1], acc[j][2], acc[j][3]);
    }
}

// ---------------------------------------------------------------------------
// Kernel D: final sum + bias + residual, float4 along w.
// ---------------------------------------------------------------------------
__global__ void __launch_bounds__(256) pw_final(const float* __restrict__ x,
                                                const float* __restrict__ pb,
                                                float* __restrict__ out) {
    int t = blockIdx.x * 256 + threadIdx.x;
    if (t >= CC * HW / 4) return;
    int o   = t / (HW / 4);
    int rem = t - o * (HW / 4);
    int h   = rem / 14;
    int w0  = (rem - h * 14) * 4;
    int gi  = o * HW + h * WW + w0;
    float4 xv = *(const float4*)(x + gi);
    float bias = pb[o];
    const int whb = (h / 7) * 8;
    const int pb7 = (h % 7) * 7;
    float vo[4];
    const float* pxv = (const float*)&xv;
    #pragma unroll
    for (int j = 0; j < 4; j++) {
        int w   = w0 + j;
        int win = whb + w / 7;
        int p   = pb7 + w % 7;
        float v = g_pwpart[((size_t)win * CC + o) * 52 + p] +
                  g_pwpart[((size_t)(64 + win) * CC + o) * 52 + p];
        vo[j] = pxv[j] + bias + v;
    }
    *(float4*)(out + gi) = make_float4(vo[0], vo[1], vo[2], vo[3]);
}

// ---------------------------------------------------------------------------
extern "C" void kernel_launch(void* const* d_in, const int* in_sizes, int n_in,
                              void* d_out, int out_size) {
    const float* x  = (const float*)d_in[0];
    const float* w3 = (const float*)d_in[1];
    const float* w5 = (const float*)d_in[2];
    const float* w7 = (const float*)d_in[3];
    const float* pw = (const float*)d_in[4];
    const float* pb = (const float*)d_in[5];
    float* out = (float*)d_out;

    cudaFuncSetAttribute(attn_kernel,
                         cudaFuncAttributeMaxDynamicSharedMemorySize, 65536);

    conv_kernel<<<384, 256>>>(x, w3, w5, w7);
    attn_kernel<<<144, 256, 65536>>>();
    pw_part<<<128, 256>>>(pw);
    pw_final<<<(CC * HW / 4 + 255) / 256, 256>>>(x, pb, out);
}